// round 6
// baseline (speedup 1.0000x reference)
#include <cuda_runtime.h>
#include <cuda_fp16.h>

#define NN 256
#define SS 64
#define BB 1024
#define UNFOLDS 12
#define TB 8
#define NPAIR (NN / 2)     // 128 i-pairs
#define NBLK  (NN / 4)     // 64 blocks of 4 i's (2 pairs)

// Scratch (device globals — no allocations allowed)
__device__ float4 g_ab[(NPAIR + 4) * NN];   // [pair][j] {a_lo, a_hi, b_lo, b_hi} f32 (padded for prefetch)
__device__ float2 g_hwe[(NPAIR + 4) * NN];  // [pair][j] {hwe_lo, hwe_hi} f32 (signed; hw = |hwe|)
__device__ float4 g_sparams[SS * NN];       // sensory {a, b, we, wsp} f32
__device__ float  g_sum_hw[NN];
__device__ float  g_sum_hwe[NN];
__device__ float  g_cmt[NN];
__device__ float  g_gl[NN];
__device__ float  g_gv[NN];

__device__ __forceinline__ float tanh_fast(float x) {
    float t;
    asm("tanh.approx.f32 %0, %1;" : "=f"(t) : "f"(x));
    return t;
}

__device__ __forceinline__ float softplus_f(float x) {
    return log1pf(expf(x));   // inputs are in small safe ranges
}

// One i-pair, one batch row. Everything f32 except the tanh itself (f16x2).
//   A  = a2 * v2 + b2                 (FFMA2, both args in one op)
//   H  = pack f16x2(A)                (F2FP)
//   T  = tanh.approx.f16x2(H)         (1 MUFU op = 2 tanh)
//   tl,th = f32(T.lo), f32(T.hi)      (F2F with half-lane select)
//   num2 += hwe2 * {tl,th}            (FFMA2, f32 accumulation)
//   den2 += |hwe2| * {tl,th}          (AND.b64 for abs, FFMA2)
__device__ __forceinline__ void proc_pair(unsigned long long v2,
                                          unsigned long long a2, unsigned long long b2,
                                          unsigned long long we2,
                                          unsigned long long& num2, unsigned long long& den2) {
    asm("{\n\t"
        ".reg .f32 lo, hi, tl, th;\n\t"
        ".reg .b16 xl, xh;\n\t"
        ".reg .b32 H, T;\n\t"
        ".reg .b64 A, TT, AH;\n\t"
        "fma.rn.f32x2 A, %2, %3, %4;\n\t"
        "mov.b64 {lo, hi}, A;\n\t"
        "cvt.rn.f16x2.f32 H, hi, lo;\n\t"
        "tanh.approx.f16x2 T, H;\n\t"
        "mov.b32 {xl, xh}, T;\n\t"
        "cvt.f32.f16 tl, xl;\n\t"
        "cvt.f32.f16 th, xh;\n\t"
        "mov.b64 TT, {tl, th};\n\t"
        "and.b64 AH, %5, 0x7FFFFFFF7FFFFFFF;\n\t"
        "fma.rn.f32x2 %0, %5, TT, %0;\n\t"
        "fma.rn.f32x2 %1, AH, TT, %1;\n\t"
        "}"
        : "+l"(num2), "+l"(den2)
        : "l"(a2), "l"(v2), "l"(b2), "l"(we2));
}

// ---------------------------------------------------------------------------
// Pack recurrent params per i-pair:
// sigmoid(s*(v-m)) = 0.5*(1 + tanh(0.5*s*v - 0.5*s*m)); hw = 0.5*softplus(w)*mask
// hwe = hw*erev (erev = ±1, so hw = |hwe|... except masked entries: hw=0 -> hwe=0, fine)
// ---------------------------------------------------------------------------
__global__ void k_prep(const float* __restrict__ w, const float* __restrict__ sigma,
                       const float* __restrict__ mu, const float* __restrict__ erev,
                       const float* __restrict__ mask) {
    int p = blockIdx.x, j = threadIdx.x;
    int x0 = (2 * p) * NN + j;
    int x1 = (2 * p + 1) * NN + j;

    float a0 = 0.5f * sigma[x0], a1 = 0.5f * sigma[x1];
    float hw0 = 0.5f * softplus_f(w[x0]) * mask[x0];
    float hw1 = 0.5f * softplus_f(w[x1]) * mask[x1];

    g_ab[p * NN + j]  = make_float4(a0, a1, -a0 * mu[x0], -a1 * mu[x1]);
    g_hwe[p * NN + j] = make_float2(hw0 * erev[x0], hw1 * erev[x1]);
}

__global__ void k_sprep(const float* __restrict__ sw, const float* __restrict__ ssig,
                        const float* __restrict__ smu, const float* __restrict__ serev,
                        const float* __restrict__ smask) {
    int s = blockIdx.x, j = threadIdx.x;
    int idx = s * NN + j;
    float wsp = softplus_f(sw[idx]) * smask[idx];
    float a   = 0.5f * ssig[idx];
    float4 q;
    q.x = a;
    q.y = -a * smu[idx];
    q.z = wsp * serev[idx];
    q.w = wsp;
    g_sparams[idx] = q;
}

// Column sums of hw/hwe + per-neuron scalars
__global__ void k_colsums(const float* __restrict__ gleak, const float* __restrict__ vleak,
                          const float* __restrict__ cm) {
    int j = threadIdx.x;
    float shw = 0.f, shwe = 0.f;
    #pragma unroll 8
    for (int p = 0; p < NPAIR; p++) {
        float2 e = g_hwe[p * NN + j];
        shwe += e.x + e.y;
        shw  += fabsf(e.x) + fabsf(e.y);
    }
    g_sum_hw[j]  = shw;
    g_sum_hwe[j] = shwe;
    float gl = softplus_f(gleak[j]);
    g_gl[j]  = gl;
    g_gv[j]  = gl * vleak[j];
    g_cmt[j] = softplus_f(cm[j]) * (float)UNFOLDS;   // softplus(cm) / (1/12)
}

// ---------------------------------------------------------------------------
// Main: each CTA owns TB=8 batch rows through all 12 unfolds.
// Prologue computes the step-invariant sensory terms inline (was k_sens).
// v lives in fp32 SMEM; inner loop reads it as 64-bit pairs (no pack MOVs).
// ---------------------------------------------------------------------------
__global__ void __launch_bounds__(256) k_main(const float* __restrict__ inputs,
                                              const float* __restrict__ state,
                                              float* __restrict__ out) {
    __shared__ float v_sh[TB][NN];
    __shared__ float xin[TB][SS];

    int j  = threadIdx.x;
    int b0 = blockIdx.x * TB;

    // load this CTA's inputs (8 rows x 64) into SMEM
    #pragma unroll
    for (int k = 0; k < (TB * SS) / NN; k++) {
        int idx = k * NN + j;
        xin[idx / SS][idx % SS] = inputs[b0 * SS + idx];
    }
    float vreg[TB];
    #pragma unroll
    for (int b = 0; b < TB; b++) {
        vreg[b] = state[(b0 + b) * NN + j];
        v_sh[b][j] = vreg[b];
    }
    __syncthreads();

    // --- inline sensory pass (step-invariant), fp32 ---
    float sn[TB], sd[TB];
    #pragma unroll
    for (int b = 0; b < TB; b++) { sn[b] = 0.f; sd[b] = 0.f; }
    #pragma unroll 2
    for (int s = 0; s < SS; s++) {
        float4 q = g_sparams[s * NN + j];
        #pragma unroll
        for (int b = 0; b < TB; b++) {
            float t  = tanh_fast(fmaf(q.x, xin[b][s], q.y));
            float sg = fmaf(0.5f, t, 0.5f);
            sn[b] = fmaf(q.z, sg, sn[b]);
            sd[b] = fmaf(q.w, sg, sd[b]);
        }
    }
    float cmt = g_cmt[j];
    float ncr[TB], dcr[TB];
    {
        float gv = g_gv[j], she = g_sum_hwe[j], gl = g_gl[j], shw = g_sum_hw[j];
        #pragma unroll
        for (int b = 0; b < TB; b++) {
            ncr[b] = gv + she + sn[b];
            dcr[b] = cmt + gl + shw + sd[b] + 1e-8f;
        }
    }

    const ulonglong2* AB = reinterpret_cast<const ulonglong2*>(g_ab) + j;   // {a2, b2}
    const unsigned long long* WE = reinterpret_cast<const unsigned long long*>(g_hwe) + j;

    for (int step = 0; step < UNFOLDS; step++) {
        unsigned long long num2[TB], den2[TB];   // f32x2 {even-i sum, odd-i sum}
        #pragma unroll
        for (int b = 0; b < TB; b++) { num2[b] = 0ull; den2[b] = 0ull; }

        // prefetch block 0 (2 pairs)
        ulonglong2 ab[2];
        unsigned long long we[2];
        #pragma unroll
        for (int p = 0; p < 2; p++) { ab[p] = AB[p * NN]; we[p] = WE[p * NN]; }

        #pragma unroll 2
        for (int blk = 0; blk < NBLK; blk++) {
            ulonglong2 cab0 = ab[0], cab1 = ab[1];
            unsigned long long cwe0 = we[0], cwe1 = we[1];

            int nb = (blk + 1 < NBLK) ? blk + 1 : blk;   // clamp last prefetch
            #pragma unroll
            for (int p = 0; p < 2; p++) {
                ab[p] = AB[(nb * 2 + p) * NN];
                we[p] = WE[(nb * 2 + p) * NN];
            }

            #pragma unroll
            for (int b = 0; b < TB; b++) {
                // 4 f32 v's = 2 pairs, one broadcast LDS.128 read as two b64s
                ulonglong2 vv = *reinterpret_cast<const ulonglong2*>(&v_sh[b][blk * 4]);
                proc_pair(vv.x, cab0.x, cab0.y, cwe0, num2[b], den2[b]);
                proc_pair(vv.y, cab1.x, cab1.y, cwe1, num2[b], den2[b]);
            }
        }

        float vn[TB];
        #pragma unroll
        for (int b = 0; b < TB; b++) {
            float nlo, nhi, dlo, dhi;
            asm("mov.b64 {%0, %1}, %2;" : "=f"(nlo), "=f"(nhi) : "l"(num2[b]));
            asm("mov.b64 {%0, %1}, %2;" : "=f"(dlo), "=f"(dhi) : "l"(den2[b]));
            float num = nlo + nhi;
            float den = dlo + dhi;
            vn[b] = (fmaf(cmt, vreg[b], ncr[b]) + num) / (den + dcr[b]);
        }

        __syncthreads();                     // all reads of v_sh done
        #pragma unroll
        for (int b = 0; b < TB; b++) {
            vreg[b] = vn[b];
            v_sh[b][j] = vn[b];
        }
        __syncthreads();
    }

    #pragma unroll
    for (int b = 0; b < TB; b++)
        out[(b0 + b) * NN + j] = vreg[b];
}

extern "C" void kernel_launch(void* const* d_in, const int* in_sizes, int n_in,
                              void* d_out, int out_size) {
    const float* inputs = (const float*)d_in[0];
    const float* state  = (const float*)d_in[1];
    const float* gleak  = (const float*)d_in[2];
    const float* vleak  = (const float*)d_in[3];
    const float* cm     = (const float*)d_in[4];
    const float* w      = (const float*)d_in[5];
    const float* sigma  = (const float*)d_in[6];
    const float* mu     = (const float*)d_in[7];
    const float* erev   = (const float*)d_in[8];
    const float* sw     = (const float*)d_in[9];
    const float* ssig   = (const float*)d_in[10];
    const float* smu    = (const float*)d_in[11];
    const float* serev  = (const float*)d_in[12];
    const float* mask   = (const float*)d_in[13];
    const float* smask  = (const float*)d_in[14];
    float* out = (float*)d_out;

    k_prep   <<<NPAIR, NN>>>(w, sigma, mu, erev, mask);
    k_sprep  <<<SS, NN>>>(sw, ssig, smu, serev, smask);
    k_colsums<<<1,  NN>>>(gleak, vleak, cm);
    k_main   <<<BB / TB, NN>>>(inputs, state, out);
}

// round 7
// speedup vs baseline: 1.4355x; 1.4355x over previous
#include <cuda_runtime.h>
#include <cuda_fp16.h>

#define NN 256
#define SS 64
#define BB 1024
#define UNFOLDS 12
#define FAST_STEPS 10          // steps 0..9 f16x2 tanh; steps 10,11 full fp32
#define TB 8
#define NPAIR (NN / 2)         // 128 i-pairs
#define NGRP 2                 // i-split groups per CTA
#define PPG (NPAIR / NGRP)     // 64 pairs per group
#define FBLK (PPG / 4)         // 16 fast blocks of 4 pairs (8 i's)

// Scratch (device globals — no allocations allowed). Padded rows for prefetch overrun.
__device__ uint2  g_ab16[(NPAIR + 8) * NN];  // [pair][j] {a2, b2} f16x2 (lo=even i, hi=odd i)
__device__ float4 g_abf [(NPAIR + 8) * NN];  // [pair][j] {a_lo, a_hi, b_lo, b_hi} f32
__device__ float2 g_hwe [(NPAIR + 8) * NN];  // [pair][j] {hwe_lo, hwe_hi} f32 (signed; hw = |hwe|)
__device__ float4 g_sparams[SS * NN];        // sensory {a, b, we, wsp} f32
__device__ float  g_sum_hw[NN];
__device__ float  g_sum_hwe[NN];
__device__ float  g_cmt[NN];
__device__ float  g_gl[NN];
__device__ float  g_gv[NN];

__device__ __forceinline__ float tanh_fast(float x) {
    float t;
    asm("tanh.approx.f32 %0, %1;" : "=f"(t) : "f"(x));
    return t;
}

__device__ __forceinline__ float softplus_f(float x) {
    return log1pf(expf(x));   // inputs are in small safe ranges
}

// One i-pair, one batch row (fast path):
//   arg2 = a2*v2 + b2 (HFMA2) ; t2 = tanh.f16x2 (1 MUFU = 2 tanh)
//   unpack to f32 ; num2 += hwe2*t (FFMA2) ; den2 += |hwe2|*t (FFMA2, abs hoisted)
__device__ __forceinline__ void proc_pair16(unsigned v2, uint2 ab,
                                            unsigned long long we2, unsigned long long wa2,
                                            unsigned long long& num2, unsigned long long& den2) {
    unsigned arg, t;
    asm("fma.rn.f16x2 %0, %1, %2, %3;" : "=r"(arg) : "r"(ab.x), "r"(v2), "r"(ab.y));
    asm("tanh.approx.f16x2 %0, %1;" : "=r"(t) : "r"(arg));
    float tlo, thi;
    asm("{ .reg .b16 l, h;\n\t"
        "  mov.b32 {l, h}, %2;\n\t"
        "  cvt.f32.f16 %0, l;\n\t"
        "  cvt.f32.f16 %1, h; }"
        : "=f"(tlo), "=f"(thi) : "r"(t));
    unsigned long long T;
    asm("mov.b64 %0, {%1, %2};" : "=l"(T) : "f"(tlo), "f"(thi));
    asm("fma.rn.f32x2 %0, %1, %2, %0;" : "+l"(num2) : "l"(we2), "l"(T));
    asm("fma.rn.f32x2 %0, %1, %2, %0;" : "+l"(den2) : "l"(wa2), "l"(T));
}

// ---------------------------------------------------------------------------
// Pack recurrent params per i-pair:
// sigmoid(s*(v-m)) = 0.5*(1 + tanh(0.5*s*v - 0.5*s*m)); hw = 0.5*softplus(w)*mask
// hwe = hw*erev (erev = ±1 -> hw = |hwe|)
// ---------------------------------------------------------------------------
__global__ void k_prep(const float* __restrict__ w, const float* __restrict__ sigma,
                       const float* __restrict__ mu, const float* __restrict__ erev,
                       const float* __restrict__ mask) {
    int p = blockIdx.x, j = threadIdx.x;
    int x0 = (2 * p) * NN + j;
    int x1 = (2 * p + 1) * NN + j;

    float a0 = 0.5f * sigma[x0], a1 = 0.5f * sigma[x1];
    float b0 = -a0 * mu[x0],     b1 = -a1 * mu[x1];
    float hw0 = 0.5f * softplus_f(w[x0]) * mask[x0];
    float hw1 = 0.5f * softplus_f(w[x1]) * mask[x1];

    __half2 A = __floats2half2_rn(a0, a1);
    __half2 Bv = __floats2half2_rn(b0, b1);
    uint2 ab;
    ab.x = *reinterpret_cast<unsigned*>(&A);
    ab.y = *reinterpret_cast<unsigned*>(&Bv);
    g_ab16[p * NN + j] = ab;
    g_abf[p * NN + j]  = make_float4(a0, a1, b0, b1);
    g_hwe[p * NN + j]  = make_float2(hw0 * erev[x0], hw1 * erev[x1]);
}

__global__ void k_sprep(const float* __restrict__ sw, const float* __restrict__ ssig,
                        const float* __restrict__ smu, const float* __restrict__ serev,
                        const float* __restrict__ smask) {
    int s = blockIdx.x, j = threadIdx.x;
    int idx = s * NN + j;
    float wsp = softplus_f(sw[idx]) * smask[idx];
    float a   = 0.5f * ssig[idx];
    g_sparams[idx] = make_float4(a, -a * smu[idx], wsp * serev[idx], wsp);
}

__global__ void k_colsums(const float* __restrict__ gleak, const float* __restrict__ vleak,
                          const float* __restrict__ cm) {
    int j = threadIdx.x;
    float shw = 0.f, shwe = 0.f;
    #pragma unroll 8
    for (int p = 0; p < NPAIR; p++) {
        float2 e = g_hwe[p * NN + j];
        shwe += e.x + e.y;
        shw  += fabsf(e.x) + fabsf(e.y);
    }
    g_sum_hw[j]  = shw;
    g_sum_hwe[j] = shwe;
    float gl = softplus_f(gleak[j]);
    g_gl[j]  = gl;
    g_gv[j]  = gl * vleak[j];
    g_cmt[j] = softplus_f(cm[j]) * (float)UNFOLDS;   // softplus(cm) / (1/12)
}

// ---------------------------------------------------------------------------
// Main: 512 threads = 2 groups x 256 j-threads. Each CTA owns TB=8 batch rows.
// Group g accumulates over pre-neurons i in [g*128, g*128+128) for ALL 8 rows;
// partials merged through SMEM; group g owns the state update for rows [4g,4g+4).
// v kept in fp32 SMEM (canonical) + half copy for the fast f16x2 path.
// Steps 0..9: f16x2 tanh. Steps 10,11: full fp32 (restores accuracy margin).
// ---------------------------------------------------------------------------
__global__ void __launch_bounds__(512) k_main(const float* __restrict__ inputs,
                                              const float* __restrict__ state,
                                              float* __restrict__ out) {
    __shared__ float  v_f[TB][NN];       // canonical fp32 state
    __shared__ __half v_h[TB][NN];       // rounded copy for HFMA2 args
    __shared__ float2 part[TB][NN];      // cross-group partial {num, den}
    __shared__ float  xin[TB][SS];

    int tid = threadIdx.x;
    int gid = tid >> 8;          // 0 or 1
    int j   = tid & 255;
    int b0  = blockIdx.x * TB;

    // inputs: 8 rows x 64 = 512 floats, one per thread
    xin[tid >> 6][tid & 63] = inputs[b0 * SS + tid];

    // state: 2048 floats, 4 per thread
    #pragma unroll
    for (int k = 0; k < 4; k++) {
        int idx = k * 512 + tid;
        float v = state[b0 * NN + idx];
        int bb = idx >> 8, jj = idx & 255;
        v_f[bb][jj] = v;
        v_h[bb][jj] = __float2half_rn(v);
    }
    __syncthreads();

    // --- sensory pass (step-invariant) for the 4 owned batches ---
    float ncr[4], dcr[4];
    {
        float sn[4] = {0.f, 0.f, 0.f, 0.f}, sd[4] = {0.f, 0.f, 0.f, 0.f};
        #pragma unroll 2
        for (int s = 0; s < SS; s++) {
            float4 q = g_sparams[s * NN + j];
            #pragma unroll
            for (int k = 0; k < 4; k++) {
                float t  = tanh_fast(fmaf(q.x, xin[gid * 4 + k][s], q.y));
                float sg = fmaf(0.5f, t, 0.5f);
                sn[k] = fmaf(q.z, sg, sn[k]);
                sd[k] = fmaf(q.w, sg, sd[k]);
            }
        }
        float gv = g_gv[j], she = g_sum_hwe[j], gl = g_gl[j], shw = g_sum_hw[j];
        float cmt0 = g_cmt[j];
        #pragma unroll
        for (int k = 0; k < 4; k++) {
            ncr[k] = gv + she + sn[k];
            dcr[k] = cmt0 + gl + shw + sd[k] + 1e-8f;
        }
    }
    float cmt = g_cmt[j];

    const int pbase = gid * PPG;         // this group's first pair
    const int ibase = gid * (NN / NGRP); // this group's first pre-neuron
    const uint2*  AB = g_ab16 + pbase * NN + j;
    const unsigned long long* WE = reinterpret_cast<const unsigned long long*>(g_hwe) + pbase * NN + j;
    const float4* ABF = g_abf + pbase * NN + j;
    const float2* WEF = g_hwe + pbase * NN + j;

    for (int step = 0; step < UNFOLDS; step++) {
        float num[TB], den[TB];

        if (step < FAST_STEPS) {
            // ---------- fast f16x2 path ----------
            unsigned long long num2[TB], den2[TB];
            #pragma unroll
            for (int b = 0; b < TB; b++) { num2[b] = 0ull; den2[b] = 0ull; }

            uint2 ab[4];
            unsigned long long we[4];
            #pragma unroll
            for (int p = 0; p < 4; p++) { ab[p] = AB[p * NN]; we[p] = WE[p * NN]; }

            for (int blk = 0; blk < FBLK; blk++) {
                uint2 cab[4];
                unsigned long long cwe[4], cwa[4];
                #pragma unroll
                for (int p = 0; p < 4; p++) {
                    cab[p] = ab[p];
                    cwe[p] = we[p];
                    asm("and.b64 %0, %1, 0x7FFFFFFF7FFFFFFF;" : "=l"(cwa[p]) : "l"(cwe[p]));
                }
                // prefetch next block (padded rows absorb the overrun)
                #pragma unroll
                for (int p = 0; p < 4; p++) {
                    ab[p] = AB[((blk + 1) * 4 + p) * NN];
                    we[p] = WE[((blk + 1) * 4 + p) * NN];
                }
                #pragma unroll
                for (int b = 0; b < TB; b++) {
                    uint4 vh = *reinterpret_cast<const uint4*>(&v_h[b][ibase + blk * 8]);
                    proc_pair16(vh.x, cab[0], cwe[0], cwa[0], num2[b], den2[b]);
                    proc_pair16(vh.y, cab[1], cwe[1], cwa[1], num2[b], den2[b]);
                    proc_pair16(vh.z, cab[2], cwe[2], cwa[2], num2[b], den2[b]);
                    proc_pair16(vh.w, cab[3], cwe[3], cwa[3], num2[b], den2[b]);
                }
            }
            #pragma unroll
            for (int b = 0; b < TB; b++) {
                float nlo, nhi, dlo, dhi;
                asm("mov.b64 {%0, %1}, %2;" : "=f"(nlo), "=f"(nhi) : "l"(num2[b]));
                asm("mov.b64 {%0, %1}, %2;" : "=f"(dlo), "=f"(dhi) : "l"(den2[b]));
                num[b] = nlo + nhi;
                den[b] = dlo + dhi;
            }
        } else {
            // ---------- accurate fp32 path (last 2 steps) ----------
            #pragma unroll
            for (int b = 0; b < TB; b++) { num[b] = 0.f; den[b] = 0.f; }

            #pragma unroll 2
            for (int sb = 0; sb < PPG / 2; sb++) {       // 2 pairs (4 i's) per iter
                float4 a0 = ABF[(sb * 2) * NN];
                float4 a1 = ABF[(sb * 2 + 1) * NN];
                float2 w0 = WEF[(sb * 2) * NN];
                float2 w1 = WEF[(sb * 2 + 1) * NN];
                #pragma unroll
                for (int b = 0; b < TB; b++) {
                    float4 v = *reinterpret_cast<const float4*>(&v_f[b][ibase + sb * 4]);
                    float t0 = tanh_fast(fmaf(a0.x, v.x, a0.z));
                    float t1 = tanh_fast(fmaf(a0.y, v.y, a0.w));
                    float t2 = tanh_fast(fmaf(a1.x, v.z, a1.z));
                    float t3 = tanh_fast(fmaf(a1.y, v.w, a1.w));
                    num[b] = fmaf(w0.x, t0, num[b]); den[b] = fmaf(fabsf(w0.x), t0, den[b]);
                    num[b] = fmaf(w0.y, t1, num[b]); den[b] = fmaf(fabsf(w0.y), t1, den[b]);
                    num[b] = fmaf(w1.x, t2, num[b]); den[b] = fmaf(fabsf(w1.x), t2, den[b]);
                    num[b] = fmaf(w1.y, t3, num[b]); den[b] = fmaf(fabsf(w1.y), t3, den[b]);
                }
            }
        }

        // write partials for the 4 batches the OTHER group owns
        int ob = (1 - gid) * 4;
        #pragma unroll
        for (int k = 0; k < 4; k++)
            part[ob + k][j] = make_float2(num[ob + k], den[ob + k]);
        __syncthreads();

        // owned batches: merge, update state
        int mb = gid * 4;
        #pragma unroll
        for (int k = 0; k < 4; k++) {
            int b = mb + k;
            float2 o = part[b][j];
            float n = num[b] + o.x;
            float d = den[b] + o.y;
            float vn = (fmaf(cmt, v_f[b][j], ncr[k]) + n) / (d + dcr[k]);
            v_f[b][j] = vn;
            v_h[b][j] = __float2half_rn(vn);
        }
        __syncthreads();
    }

    // owner writes its 4 rows
    #pragma unroll
    for (int k = 0; k < 4; k++) {
        int b = gid * 4 + k;
        out[(b0 + b) * NN + j] = v_f[b][j];
    }
}

extern "C" void kernel_launch(void* const* d_in, const int* in_sizes, int n_in,
                              void* d_out, int out_size) {
    const float* inputs = (const float*)d_in[0];
    const float* state  = (const float*)d_in[1];
    const float* gleak  = (const float*)d_in[2];
    const float* vleak  = (const float*)d_in[3];
    const float* cm     = (const float*)d_in[4];
    const float* w      = (const float*)d_in[5];
    const float* sigma  = (const float*)d_in[6];
    const float* mu     = (const float*)d_in[7];
    const float* erev   = (const float*)d_in[8];
    const float* sw     = (const float*)d_in[9];
    const float* ssig   = (const float*)d_in[10];
    const float* smu    = (const float*)d_in[11];
    const float* serev  = (const float*)d_in[12];
    const float* mask   = (const float*)d_in[13];
    const float* smask  = (const float*)d_in[14];
    float* out = (float*)d_out;

    k_prep   <<<NPAIR, NN>>>(w, sigma, mu, erev, mask);
    k_sprep  <<<SS, NN>>>(sw, ssig, smu, serev, smask);
    k_colsums<<<1,  NN>>>(gleak, vleak, cm);
    k_main   <<<BB / TB, 512>>>(inputs, state, out);
}